// round 16
// baseline (speedup 1.0000x reference)
#include <cuda_runtime.h>

#define NCH   96
#define NRF   25
#define HALF  12
#define IMH   55
#define IMW   55
#define NB    128
#define POS   (IMH*IMW)          // 3025
#define MAXPLANES 6
#define MAXTAPS   40
#define KELEMS (NRF*NRF)         // 625
#define KCHUNKS 20
#define PW    (IMW + 2*HALF)     // 79
#define PH    (IMH + 2*HALF)     // 79
#define SIMG  (PW*PH)            // 6241
#define SIMGP 6244               // padded to float4 multiple
#define SIMG4 (SIMGP/4)          // 1561

struct __align__(8) Tap { int off; float w; };   // off = dr*PW + dc

// ---- device-global state (static scratch; no allocations) ----
// g_planes_pad: BSS zero-initialized. Gather writes ONLY the 55x55 interior;
// the 12-wide pads stay zero forever -> SAME padding for free, replay-safe.
__device__ int   g_cnt_ch[NCH];
__device__ Tap   g_taps_ch[NCH][MAXTAPS];
__device__ int   g_nplanes;
__device__ int   g_plane_ch[NCH < MAXPLANES ? NCH : MAXPLANES];
__device__ int   g_chplane[NCH];
__device__ float g_chmask[NCH];
__device__ float g_planes_pad[NB][MAXPLANES][SIMGP];  // 19.2 MB padded planes
__device__ float g_lat[NB][MAXPLANES][POS];           // 9.3 MB lateral sums

// ---------------------------------------------------------------------------
// 1) Extract: one warp per channel; preloaded MLP=20, ballot ranks.
// ---------------------------------------------------------------------------
__global__ void __launch_bounds__(32) extract_kernel(const float* __restrict__ k) {
    const int c = blockIdx.x;
    const int lane = threadIdx.x;
    float v[KCHUNKS];
    #pragma unroll
    for (int j = 0; j < KCHUNKS; j++) {
        const int i = j * 32 + lane;
        v[j] = (i < KELEMS) ? __ldg(&k[c * KELEMS + i]) : 0.0f;
    }
    int total = 0;
    #pragma unroll
    for (int j = 0; j < KCHUNKS; j++) {
        const int i = j * 32 + lane;
        const unsigned m = __ballot_sync(0xFFFFFFFFu, v[j] != 0.0f);
        if (v[j] != 0.0f) {
            const int rank = total + __popc(m & ((1u << lane) - 1u));
            if (rank < MAXTAPS) {
                Tap t;
                t.off = (i / NRF - HALF) * PW + (i % NRF - HALF);
                t.w   = v[j];
                g_taps_ch[c][rank] = t;
            }
        }
        total += __popc(m);
    }
    if (lane == 0) g_cnt_ch[c] = (total < MAXTAPS) ? total : MAXTAPS;
}

// ---------------------------------------------------------------------------
// 2) Plan: tiny serial pass -> plane list + per-channel mask/plane.
// ---------------------------------------------------------------------------
__global__ void plan_kernel() {
    __shared__ int pid[NCH];
    const int tid = threadIdx.x;           // 128 threads
    if (tid == 0) {
        int np = 0;
        for (int cc = 0; cc < NCH; cc++) {
            if (g_cnt_ch[cc] > 0 && np < MAXPLANES) {
                pid[cc] = np;
                g_plane_ch[np] = cc;
                np++;
            } else pid[cc] = -1;
        }
        g_nplanes = np;
    }
    __syncthreads();
    if (tid < NCH) {
        const int p = pid[tid];
        g_chplane[tid] = (p >= 0) ? p : 0;
        g_chmask[tid]  = (p >= 0) ? 1.0f : 0.0f;
    }
}

// ---------------------------------------------------------------------------
// 3) Gather: lane-cooperative channel grouping, writes PADDED interior.
//    lane&7 = plane, lane>>3 = position offset: warp covers 4 positions x
//    6 channels on ~12 unique 128B lines. Pads of g_planes_pad stay zero.
// ---------------------------------------------------------------------------
#define GT 256
#define GPOS_PER_BLOCK 32                    // 8 warps * 4 positions
#define GBLOCKS ((NB * POS + GPOS_PER_BLOCK - 1) / GPOS_PER_BLOCK)   // 12100

__global__ void __launch_bounds__(GT) gather_kernel(const float* __restrict__ x) {
    const int tid  = threadIdx.x;
    const int wid  = tid >> 5;
    const int lane = tid & 31;
    const int p    = lane & 7;               // plane slot (6,7 idle)
    const int po   = lane >> 3;              // position offset within warp

    const int posIdx = blockIdx.x * GPOS_PER_BLOCK + wid * 4 + po;   // n*POS+pos
    if (posIdx >= NB * POS) return;
    if (p >= g_nplanes) return;

    const int ch = g_plane_ch[p];
    const float val = __ldg(&x[(size_t)posIdx * NCH + ch]);

    const int n   = posIdx / POS;
    const int pos = posIdx - n * POS;
    const int h   = pos / IMW;
    const int w   = pos - h * IMW;
    g_planes_pad[n][p][(h + HALF) * PW + (w + HALF)] = val;
}

// ---------------------------------------------------------------------------
// 4) Latcomp: block per (image, plane). Stage = ONE coalesced float4 copy of
//    the padded plane (zero pads included); tap loop with precomputed linear
//    offsets -> g_lat. No zero-fill, no scattered smem writes, no div in stage.
// ---------------------------------------------------------------------------
#define LCT 256
#define LC_LD ((POS + LCT - 1) / LCT)    // 12

__global__ void __launch_bounds__(LCT) latcomp_kernel() {
    __shared__ __align__(16) float s_img[SIMGP];   // 24.98 KB
    __shared__ Tap   s_taps[MAXTAPS];
    __shared__ int   s_nt;

    const int tid = threadIdx.x;
    const int n   = blockIdx.x;
    const int p   = blockIdx.y;
    if (p >= g_nplanes) return;          // uniform per block

    if (tid == 0) s_nt = g_cnt_ch[g_plane_ch[p]];
    if (tid < MAXTAPS) s_taps[tid] = g_taps_ch[g_plane_ch[p]][tid];

    // coalesced staged copy of the full padded plane (1561 float4)
    const float4* src4 = (const float4*)&g_planes_pad[n][p][0];
    float4* dst4 = (float4*)s_img;
    #pragma unroll
    for (int g = tid; g < SIMG4; g += LCT)
        dst4[g] = src4[g];
    __syncthreads();

    const int nt = s_nt;
    #pragma unroll
    for (int j = 0; j < LC_LD; j++) {
        const int i = tid + j * LCT;
        if (i < POS) {
            const int h = i / IMW;
            const int w = i - h * IMW;
            const float* base = s_img + (h + HALF) * PW + (w + HALF);
            float acc = 0.0f;
            #pragma unroll 4
            for (int t = 0; t < nt; t++)
                acc += s_taps[t].w * base[s_taps[t].off];
            g_lat[n][p][i] = acc;
        }
    }
}

// ---------------------------------------------------------------------------
// 5) Stream: persistent row-tile kernel, double-buffered s_lat.
// ---------------------------------------------------------------------------
#define STR_THREADS 240
#define STR_BLOCKS  1184              // 148 SMs * 8 blocks
#define NTILES      (NB * IMH)        // 7040 row tiles
#define ROWV4       (IMW * NCH / 4)   // 1320 float4 per row

__global__ void __launch_bounds__(STR_THREADS, 8) stream_kernel(
    const float* __restrict__ x, float* __restrict__ out)
{
    __shared__ float s_lat[2][MAXPLANES * IMW];   // 2.6 KB

    const int tid = threadIdx.x;
    const int np  = g_nplanes;

    const int c4   = tid % 24;
    const int pos0 = tid / 24;        // 0..9
    const int c0   = c4 * 4;
    const float m0 = g_chmask[c0+0], m1 = g_chmask[c0+1], m2 = g_chmask[c0+2], m3 = g_chmask[c0+3];
    const int   o0 = g_chplane[c0+0] * IMW, o1 = g_chplane[c0+1] * IMW,
                o2 = g_chplane[c0+2] * IMW, o3 = g_chplane[c0+3] * IMW;

    const int nlat = np * IMW;

    int t0 = blockIdx.x;
    if (t0 < NTILES) {
        const int n = t0 / IMH, h = t0 - n * IMH;
        for (int j = tid; j < nlat; j += STR_THREADS) {
            const int p = j / IMW;
            s_lat[0][j] = __ldcs(&g_lat[n][p][h * IMW + (j - p * IMW)]);
        }
    }
    __syncthreads();

    int buf = 0;
    for (int t = t0; t < NTILES; t += STR_BLOCKS) {
        const int tn = t + STR_BLOCKS;
        if (tn < NTILES) {
            const int n2 = tn / IMH, h2 = tn - n2 * IMH;
            for (int j = tid; j < nlat; j += STR_THREADS) {
                const int p = j / IMW;
                s_lat[buf ^ 1][j] = __ldcs(&g_lat[n2][p][h2 * IMW + (j - p * IMW)]);
            }
        }

        const int n = t / IMH, h = t - n * IMH;
        const int base = (n * IMH + h) * ROWV4;
        const float4* x4 = (const float4*)x + base;
        float4*       o4 = (float4*)out + base;
        const float* L = s_lat[buf];

        #pragma unroll
        for (int kk = 0; kk < 6; kk++) {          // 1320 = 240*5.5
            const int i   = tid + 240 * kk;
            const int pos = pos0 + 10 * kk;
            if (i < ROWV4) {
                float4 v = __ldcs(&x4[i]);
                v.x += m0 * L[o0 + pos];
                v.y += m1 * L[o1 + pos];
                v.z += m2 * L[o2 + pos];
                v.w += m3 * L[o3 + pos];
                __stcs(&o4[i], v);
            }
        }
        __syncthreads();
        buf ^= 1;
    }
}

extern "C" void kernel_launch(void* const* d_in, const int* in_sizes, int n_in,
                              void* d_out, int out_size) {
    const float* x = (const float*)d_in[0];   // [128,55,55,96] f32
    const float* k = (const float*)d_in[1];   // [96,25,25] f32
    float* out = (float*)d_out;
    (void)in_sizes; (void)n_in; (void)out_size;

    extract_kernel<<<NCH, 32>>>(k);
    plan_kernel<<<1, 128>>>();
    gather_kernel<<<GBLOCKS, GT>>>(x);
    latcomp_kernel<<<dim3(NB, MAXPLANES), LCT>>>();
    stream_kernel<<<STR_BLOCKS, STR_THREADS>>>(x, out);
}

// round 17
// speedup vs baseline: 1.0641x; 1.0641x over previous
#include <cuda_runtime.h>

#define NCH   96
#define NRF   25
#define HALF  12
#define IMH   55
#define IMW   55
#define NB    128
#define POS   (IMH*IMW)          // 3025
#define POSP  3028               // float4/float2-aligned plane stride
#define NPAIR 1513               // ceil(POS/2) position-pairs per image
#define MAXPLANES 6
#define MAXTAPS   40
#define KELEMS (NRF*NRF)         // 625
#define KCHUNKS 20
#define PW    (IMW + 2*HALF)     // 79
#define PH    (IMH + 2*HALF)     // 79
#define SIMG  (PW*PH)            // 6241

struct __align__(8) Tap { int off; float w; };   // off = dr*PW + dc

// ---- device-global state (static scratch; no allocations) ----
__device__ int   g_cnt_ch[NCH];
__device__ Tap   g_taps_ch[NCH][MAXTAPS];
__device__ int   g_nplanes;
__device__ int   g_plane_ch[MAXPLANES];
__device__ int   g_chplane[NCH];
__device__ float g_chmask[NCH];
__device__ int   g_sync_ctr;                     // BSS zero; reset after use
__device__ float g_planes[NB][MAXPLANES][POSP];  // compact planes
__device__ float g_lat[NB][MAXPLANES][POS];      // lateral sums

// ---------------------------------------------------------------------------
// 1) Extract+Plan: one warp per channel; the LAST finishing block runs the
//    serial plan (threadfence-reduction pattern) and resets the counter so
//    graph replays start clean.
// ---------------------------------------------------------------------------
__global__ void __launch_bounds__(32) extract_kernel(const float* __restrict__ k) {
    __shared__ int s_pid[NCH];
    const int c = blockIdx.x;
    const int lane = threadIdx.x;
    float v[KCHUNKS];
    #pragma unroll
    for (int j = 0; j < KCHUNKS; j++) {
        const int i = j * 32 + lane;
        v[j] = (i < KELEMS) ? __ldg(&k[c * KELEMS + i]) : 0.0f;
    }
    int total = 0;
    #pragma unroll
    for (int j = 0; j < KCHUNKS; j++) {
        const int i = j * 32 + lane;
        const unsigned m = __ballot_sync(0xFFFFFFFFu, v[j] != 0.0f);
        if (v[j] != 0.0f) {
            const int rank = total + __popc(m & ((1u << lane) - 1u));
            if (rank < MAXTAPS) {
                Tap t;
                t.off = (i / NRF - HALF) * PW + (i % NRF - HALF);
                t.w   = v[j];
                g_taps_ch[c][rank] = t;
            }
        }
        total += __popc(m);
    }
    if (lane == 0) g_cnt_ch[c] = (total < MAXTAPS) ? total : MAXTAPS;

    // --- last-block-done plan ---
    __threadfence();
    int old = 0;
    if (lane == 0) old = atomicAdd(&g_sync_ctr, 1);
    old = __shfl_sync(0xFFFFFFFFu, old, 0);
    if (old == NCH - 1) {
        if (lane == 0) {
            int np = 0;
            for (int cc = 0; cc < NCH; cc++) {
                if (g_cnt_ch[cc] > 0 && np < MAXPLANES) {
                    s_pid[cc] = np;
                    g_plane_ch[np] = cc;
                    np++;
                } else s_pid[cc] = -1;
            }
            g_nplanes = np;
            g_sync_ctr = 0;              // reset for next graph replay
        }
        __syncwarp();
        #pragma unroll
        for (int base = 0; base < NCH; base += 32) {
            const int cc = base + lane;
            const int p = s_pid[cc];
            g_chplane[cc] = (p >= 0) ? p : 0;
            g_chmask[cc]  = (p >= 0) ? 1.0f : 0.0f;
        }
        __threadfence();
    }
}

// ---------------------------------------------------------------------------
// 2) Gather v3: lane-cooperative channel grouping, 2 consecutive positions
//    per thread (pairs within-image). lane&7 = plane, lane>>3 = pair offset.
//    Warp covers 8 positions x 6 channels; float2 stores to compact planes.
// ---------------------------------------------------------------------------
#define GT 256
#define GPAIRS_PER_BLOCK 32                  // 8 warps * 4 pairs
#define GTOTPAIR (NB * NPAIR)                // 193,664
#define GBLOCKS ((GTOTPAIR + GPAIRS_PER_BLOCK - 1) / GPAIRS_PER_BLOCK)   // 6053

__global__ void __launch_bounds__(GT) gather_kernel(const float* __restrict__ x) {
    const int tid  = threadIdx.x;
    const int wid  = tid >> 5;
    const int lane = tid & 31;
    const int p    = lane & 7;               // plane slot (6,7 idle)
    const int po   = lane >> 3;              // pair offset within warp (0-3)

    const int pairIdx = blockIdx.x * GPAIRS_PER_BLOCK + wid * 4 + po;
    if (pairIdx >= GTOTPAIR) return;
    if (p >= g_nplanes) return;

    const int n    = pairIdx / NPAIR;
    const int pr   = pairIdx - n * NPAIR;
    const int pos0 = pr * 2;                 // pos0 < 3025 always
    const int ch   = g_plane_ch[p];

    const float* xb = x + ((size_t)n * POS + pos0) * NCH + ch;
    const float v0 = __ldg(xb);
    if (pos0 + 1 < POS) {
        const float v1 = __ldg(xb + NCH);
        *(float2*)&g_planes[n][p][pos0] = make_float2(v0, v1);
    } else {
        g_planes[n][p][pos0] = v0;
    }
}

// ---------------------------------------------------------------------------
// 3) Latcomp (R15-measured-best): block per (image, plane). Zero-padded
//    79x79 smem image, precomputed linear tap offsets, no bounds checks.
// ---------------------------------------------------------------------------
#define LCT 256
#define LC_LD ((POS + LCT - 1) / LCT)    // 12

__global__ void __launch_bounds__(LCT) latcomp_kernel() {
    __shared__ float s_img[SIMG];        // 24.96 KB
    __shared__ Tap   s_taps[MAXTAPS];
    __shared__ int   s_nt;

    const int tid = threadIdx.x;
    const int n   = blockIdx.x;
    const int p   = blockIdx.y;
    if (p >= g_nplanes) return;          // uniform per block

    if (tid == 0) s_nt = g_cnt_ch[g_plane_ch[p]];
    if (tid < MAXTAPS) s_taps[tid] = g_taps_ch[g_plane_ch[p]][tid];

    for (int j = tid; j < SIMG; j += LCT) s_img[j] = 0.0f;
    __syncthreads();
    const float* src = &g_planes[n][p][0];
    #pragma unroll
    for (int j = 0; j < LC_LD; j++) {
        const int i = tid + j * LCT;
        if (i < POS) {
            const int h = i / IMW;
            const int w = i - h * IMW;
            s_img[(h + HALF) * PW + (w + HALF)] = src[i];
        }
    }
    __syncthreads();

    const int nt = s_nt;
    #pragma unroll
    for (int j = 0; j < LC_LD; j++) {
        const int i = tid + j * LCT;
        if (i < POS) {
            const int h = i / IMW;
            const int w = i - h * IMW;
            const float* base = s_img + (h + HALF) * PW + (w + HALF);
            float acc = 0.0f;
            #pragma unroll 4
            for (int t = 0; t < nt; t++)
                acc += s_taps[t].w * base[s_taps[t].off];
            g_lat[n][p][i] = acc;
        }
    }
}

// ---------------------------------------------------------------------------
// 4) Stream (R15-measured-best): persistent row-tile kernel, double-buffered.
// ---------------------------------------------------------------------------
#define STR_THREADS 240
#define STR_BLOCKS  1184              // 148 SMs * 8 blocks
#define NTILES      (NB * IMH)        // 7040 row tiles
#define ROWV4       (IMW * NCH / 4)   // 1320 float4 per row

__global__ void __launch_bounds__(STR_THREADS, 8) stream_kernel(
    const float* __restrict__ x, float* __restrict__ out)
{
    __shared__ float s_lat[2][MAXPLANES * IMW];   // 2.6 KB

    const int tid = threadIdx.x;
    const int np  = g_nplanes;

    const int c4   = tid % 24;
    const int pos0 = tid / 24;        // 0..9
    const int c0   = c4 * 4;
    const float m0 = g_chmask[c0+0], m1 = g_chmask[c0+1], m2 = g_chmask[c0+2], m3 = g_chmask[c0+3];
    const int   o0 = g_chplane[c0+0] * IMW, o1 = g_chplane[c0+1] * IMW,
                o2 = g_chplane[c0+2] * IMW, o3 = g_chplane[c0+3] * IMW;

    const int nlat = np * IMW;

    int t0 = blockIdx.x;
    if (t0 < NTILES) {
        const int n = t0 / IMH, h = t0 - n * IMH;
        for (int j = tid; j < nlat; j += STR_THREADS) {
            const int p = j / IMW;
            s_lat[0][j] = __ldcs(&g_lat[n][p][h * IMW + (j - p * IMW)]);
        }
    }
    __syncthreads();

    int buf = 0;
    for (int t = t0; t < NTILES; t += STR_BLOCKS) {
        const int tn = t + STR_BLOCKS;
        if (tn < NTILES) {
            const int n2 = tn / IMH, h2 = tn - n2 * IMH;
            for (int j = tid; j < nlat; j += STR_THREADS) {
                const int p = j / IMW;
                s_lat[buf ^ 1][j] = __ldcs(&g_lat[n2][p][h2 * IMW + (j - p * IMW)]);
            }
        }

        const int n = t / IMH, h = t - n * IMH;
        const int base = (n * IMH + h) * ROWV4;
        const float4* x4 = (const float4*)x + base;
        float4*       o4 = (float4*)out + base;
        const float* L = s_lat[buf];

        #pragma unroll
        for (int kk = 0; kk < 6; kk++) {          // 1320 = 240*5.5
            const int i   = tid + 240 * kk;
            const int pos = pos0 + 10 * kk;
            if (i < ROWV4) {
                float4 v = __ldcs(&x4[i]);
                v.x += m0 * L[o0 + pos];
                v.y += m1 * L[o1 + pos];
                v.z += m2 * L[o2 + pos];
                v.w += m3 * L[o3 + pos];
                __stcs(&o4[i], v);
            }
        }
        __syncthreads();
        buf ^= 1;
    }
}

extern "C" void kernel_launch(void* const* d_in, const int* in_sizes, int n_in,
                              void* d_out, int out_size) {
    const float* x = (const float*)d_in[0];   // [128,55,55,96] f32
    const float* k = (const float*)d_in[1];   // [96,25,25] f32
    float* out = (float*)d_out;
    (void)in_sizes; (void)n_in; (void)out_size;

    extract_kernel<<<NCH, 32>>>(k);
    gather_kernel<<<GBLOCKS, GT>>>(x);
    latcomp_kernel<<<dim3(NB, MAXPLANES), LCT>>>();
    stream_kernel<<<STR_BLOCKS, STR_THREADS>>>(x, out);
}